// round 1
// baseline (speedup 1.0000x reference)
#include <cuda_runtime.h>
#include <cuda_bf16.h>

#define NN   100000
#define EE   1600000
#define DIN_ 128
#define DH_  128
#define DOUT_ 64

// Scratch (static device globals — allocation is forbidden in kernel_launch)
__device__ float g_deg[NN];
__device__ float g_dinv[NN];
__device__ float g_norm[EE];
__device__ float g_h1[(size_t)NN * DH_];    // x @ W1
__device__ float g_agg1[(size_t)NN * DH_];  // aggregated layer-1 (pre-relu)
__device__ float g_h2[(size_t)NN * DOUT_];  // relu(agg1) @ W2

// ---------------------------------------------------------------------------
// degree / norm kernels
// ---------------------------------------------------------------------------
__global__ void k_init_deg(int n) {
    int i = blockIdx.x * blockDim.x + threadIdx.x;
    if (i < n) g_deg[i] = 1.0f;  // self-loop
}

__global__ void k_count_deg(const int* __restrict__ dst, int e) {
    int i = blockIdx.x * blockDim.x + threadIdx.x;
    if (i < e) {
        float* p = &g_deg[dst[i]];
        asm volatile("red.global.add.f32 [%0], %1;" :: "l"(p), "f"(1.0f) : "memory");
    }
}

__global__ void k_dinv(int n) {
    int i = blockIdx.x * blockDim.x + threadIdx.x;
    if (i < n) g_dinv[i] = rsqrtf(g_deg[i]);
}

__global__ void k_norm(const int* __restrict__ src, const int* __restrict__ dst, int e) {
    int i = blockIdx.x * blockDim.x + threadIdx.x;
    if (i < e) g_norm[i] = g_dinv[src[i]] * g_dinv[dst[i]];
}

// ---------------------------------------------------------------------------
// GEMM: C[n, DC] = A[n, 128] @ W[128, DC]   (optional relu on A load)
// block: 128 threads, 64 rows per block. W + A tile in dynamic smem.
// Each thread: column c = tid % DC, handles 8 rows at a time (8 independent
// accumulators to hide FMA latency), float4 loads on A over k.
// ---------------------------------------------------------------------------
template <int DC, bool RELU>
__global__ void k_gemm(const float* __restrict__ A, const float* __restrict__ W,
                       float* __restrict__ C, int nrows) {
    extern __shared__ float smem[];
    float* Ws = smem;              // 128 * DC
    float* As = smem + 128 * DC;   // 64 * 128

    const int BR = 64;
    int row0 = blockIdx.x * BR;
    int rows = nrows - row0; if (rows > BR) rows = BR;

    // load W (128*DC floats) via float4
    for (int i = threadIdx.x; i < 128 * DC / 4; i += blockDim.x)
        ((float4*)Ws)[i] = ((const float4*)W)[i];

    // load A tile (rows*128 floats) via float4, optional relu
    for (int i = threadIdx.x; i < rows * 32; i += blockDim.x) {
        float4 v = ((const float4*)(A + (size_t)row0 * 128))[i];
        if (RELU) {
            v.x = fmaxf(v.x, 0.f); v.y = fmaxf(v.y, 0.f);
            v.z = fmaxf(v.z, 0.f); v.w = fmaxf(v.w, 0.f);
        }
        ((float4*)As)[i] = v;
    }
    __syncthreads();

    const int G = 128 / DC;          // row groups (1 for DC=128, 2 for DC=64)
    int c = threadIdx.x % DC;
    int g = threadIdx.x / DC;

    for (int rc = g * 8; rc < BR; rc += 8 * G) {
        if (row0 + rc >= nrows) break;
        float acc[8];
#pragma unroll
        for (int r = 0; r < 8; r++) acc[r] = 0.f;

        for (int k = 0; k < 128; k += 4) {
            float w0 = Ws[(k + 0) * DC + c];
            float w1 = Ws[(k + 1) * DC + c];
            float w2 = Ws[(k + 2) * DC + c];
            float w3 = Ws[(k + 3) * DC + c];
#pragma unroll
            for (int r = 0; r < 8; r++) {
                float4 a = *(const float4*)&As[(rc + r) * 128 + k];
                acc[r] = fmaf(a.x, w0, acc[r]);
                acc[r] = fmaf(a.y, w1, acc[r]);
                acc[r] = fmaf(a.z, w2, acc[r]);
                acc[r] = fmaf(a.w, w3, acc[r]);
            }
        }
#pragma unroll
        for (int r = 0; r < 8; r++) {
            int row = row0 + rc + r;
            if (row < nrows) C[(size_t)row * DC + c] = acc[r];
        }
    }
}

// ---------------------------------------------------------------------------
// self-loop init: agg[i,:] = h[i,:] * dinv[i]^2 + b
// ---------------------------------------------------------------------------
__global__ void k_self_init128(const float* __restrict__ h, const float* __restrict__ b,
                               float* __restrict__ agg, int n) {
    int i = blockIdx.x * blockDim.x + threadIdx.x;      // over n*32 float4s
    if (i >= n * 32) return;
    int node = i >> 5, j = i & 31;
    float s = g_dinv[node]; s = s * s;
    float4 v = ((const float4*)h)[i];
    float4 bb = ((const float4*)b)[j];
    v.x = fmaf(v.x, s, bb.x); v.y = fmaf(v.y, s, bb.y);
    v.z = fmaf(v.z, s, bb.z); v.w = fmaf(v.w, s, bb.w);
    ((float4*)agg)[i] = v;
}

__global__ void k_self_init64(const float* __restrict__ h, const float* __restrict__ b,
                              float* __restrict__ agg, int n) {
    int i = blockIdx.x * blockDim.x + threadIdx.x;      // over n*16 float4s
    if (i >= n * 16) return;
    int node = i >> 4, j = i & 15;
    float s = g_dinv[node]; s = s * s;
    float4 v = ((const float4*)h)[i];
    float4 bb = ((const float4*)b)[j];
    v.x = fmaf(v.x, s, bb.x); v.y = fmaf(v.y, s, bb.y);
    v.z = fmaf(v.z, s, bb.z); v.w = fmaf(v.w, s, bb.w);
    ((float4*)agg)[i] = v;
}

// ---------------------------------------------------------------------------
// edge aggregation: warp per edge.
// agg[dst,:] += h[src,:] * norm[e]   via red.global.add.v4/v2.f32
// ---------------------------------------------------------------------------
__global__ void k_edge128(const float* __restrict__ h, const int* __restrict__ src,
                          const int* __restrict__ dst, float* __restrict__ agg, int e) {
    int w = (blockIdx.x * blockDim.x + threadIdx.x) >> 5;
    int lane = threadIdx.x & 31;
    if (w >= e) return;
    int s = src[w], d = dst[w];
    float nv = g_norm[w];
    float4 v = *(const float4*)(h + (size_t)s * 128 + lane * 4);
    v.x *= nv; v.y *= nv; v.z *= nv; v.w *= nv;
    float* p = agg + (size_t)d * 128 + lane * 4;
    asm volatile("red.global.add.v4.f32 [%0], {%1,%2,%3,%4};"
                 :: "l"(p), "f"(v.x), "f"(v.y), "f"(v.z), "f"(v.w) : "memory");
}

__global__ void k_edge64(const float* __restrict__ h, const int* __restrict__ src,
                         const int* __restrict__ dst, float* __restrict__ agg, int e) {
    int w = (blockIdx.x * blockDim.x + threadIdx.x) >> 5;
    int lane = threadIdx.x & 31;
    if (w >= e) return;
    int s = src[w], d = dst[w];
    float nv = g_norm[w];
    float2 v = *(const float2*)(h + (size_t)s * 64 + lane * 2);
    v.x *= nv; v.y *= nv;
    float* p = agg + (size_t)d * 64 + lane * 2;
    asm volatile("red.global.add.v2.f32 [%0], {%1,%2};"
                 :: "l"(p), "f"(v.x), "f"(v.y) : "memory");
}

// ---------------------------------------------------------------------------
extern "C" void kernel_launch(void* const* d_in, const int* in_sizes, int n_in,
                              void* d_out, int out_size) {
    const float* x  = (const float*)d_in[0];
    const int*   ei = (const int*)d_in[1];
    const float* W1 = (const float*)d_in[2];
    const float* b1 = (const float*)d_in[3];
    const float* W2 = (const float*)d_in[4];
    const float* b2 = (const float*)d_in[5];
    float* out = (float*)d_out;

    int n = in_sizes[0] / DIN_;
    int e = in_sizes[1] / 2;
    const int* src = ei;
    const int* dst = ei + e;

    // dynamic smem opt-in (idempotent host calls; not stream ops)
    cudaFuncSetAttribute(k_gemm<128, false>, cudaFuncAttributeMaxDynamicSharedMemorySize,
                         (128 * 128 + 64 * 128) * 4);
    cudaFuncSetAttribute(k_gemm<64, true>, cudaFuncAttributeMaxDynamicSharedMemorySize,
                         (128 * 64 + 64 * 128) * 4);

    const int T = 256;

    // degrees + norms
    k_init_deg<<<(n + T - 1) / T, T>>>(n);
    k_count_deg<<<(e + T - 1) / T, T>>>(dst, e);
    k_dinv<<<(n + T - 1) / T, T>>>(n);
    k_norm<<<(e + T - 1) / T, T>>>(src, dst, e);

    // layer 1: h1 = x @ W1 ; agg1 = self + scatter
    k_gemm<128, false><<<(n + 63) / 64, 128, (128 * 128 + 64 * 128) * 4>>>(x, W1, g_h1, n);
    k_self_init128<<<(n * 32 + T - 1) / T, T>>>(g_h1, b1, g_agg1, n);
    k_edge128<<<(e + 7) / 8, T>>>(g_h1, src, dst, g_agg1, e);

    // layer 2: h2 = relu(agg1) @ W2 ; out = self + scatter
    k_gemm<64, true><<<(n + 63) / 64, 128, (128 * 64 + 64 * 128) * 4>>>(g_agg1, W2, g_h2, n);
    k_self_init64<<<(n * 16 + T - 1) / T, T>>>(g_h2, b2, out, n);
    k_edge64<<<(e + 7) / 8, T>>>(g_h2, src, dst, out, e);
}

// round 2
// speedup vs baseline: 1.6165x; 1.6165x over previous
#include <cuda_runtime.h>
#include <cuda_bf16.h>

#define NN    100000
#define EE    1600000
#define DIN_  128
#define DH_   128
#define DOUT_ 64

// ---------------------------------------------------------------------------
// Scratch (static device globals — allocation forbidden in kernel_launch)
// ---------------------------------------------------------------------------
__device__ int   g_cnt[NN];          // in-degree counts, then reused as cursor
__device__ int   g_rowptr[NN + 1];   // CSR row pointers (by dst)
__device__ int   g_eidx[EE];         // src node per CSR slot
__device__ float g_dinv[NN];
__device__ float g_hs1[(size_t)NN * DH_];    // (x @ W1) * dinv[row]
__device__ float g_agg1[(size_t)NN * DH_];   // layer-1 output (pre-relu)
__device__ float g_hs2[(size_t)NN * DOUT_];  // (relu(agg1) @ W2) * dinv[row]

// ---------------------------------------------------------------------------
// CSR construction
// ---------------------------------------------------------------------------
__global__ void k_zero_cnt(int n) {
    int i = blockIdx.x * blockDim.x + threadIdx.x;
    if (i < n) g_cnt[i] = 0;
}

__global__ void k_count(const int* __restrict__ dst, int e) {
    int i = blockIdx.x * blockDim.x + threadIdx.x;
    if (i < e) atomicAdd(&g_cnt[dst[i]], 1);
}

__global__ void k_dinv(int n) {
    int i = blockIdx.x * blockDim.x + threadIdx.x;
    if (i < n) g_dinv[i] = rsqrtf((float)g_cnt[i] + 1.0f);
}

// single-block exclusive scan over g_cnt -> g_rowptr (n up to ~1M fine)
__global__ void k_scan(int n) {
    __shared__ int sh[1024];
    __shared__ int carry;
    if (threadIdx.x == 0) carry = 0;
    __syncthreads();
    for (int base = 0; base < n; base += 1024) {
        int i = base + (int)threadIdx.x;
        int v = (i < n) ? g_cnt[i] : 0;
        sh[threadIdx.x] = v;
        __syncthreads();
#pragma unroll
        for (int ofs = 1; ofs < 1024; ofs <<= 1) {
            int t = (threadIdx.x >= ofs) ? sh[threadIdx.x - ofs] : 0;
            __syncthreads();
            sh[threadIdx.x] += t;
            __syncthreads();
        }
        if (i < n) g_rowptr[i] = carry + sh[threadIdx.x] - v;  // exclusive
        __syncthreads();
        if (threadIdx.x == 1023) carry += sh[1023];
        __syncthreads();
    }
    if (threadIdx.x == 0) g_rowptr[n] = carry;
}

__global__ void k_copycur(int n) {
    int i = blockIdx.x * blockDim.x + threadIdx.x;
    if (i < n) g_cnt[i] = g_rowptr[i];
}

__global__ void k_fill(const int* __restrict__ src, const int* __restrict__ dst, int e) {
    int i = blockIdx.x * blockDim.x + threadIdx.x;
    if (i < e) {
        int pos = atomicAdd(&g_cnt[dst[i]], 1);
        g_eidx[pos] = src[i];
    }
}

// ---------------------------------------------------------------------------
// GEMM: C[row, :] = (relu?)(A[row, :]) @ W[128, DC] * dinv[row]
// block = 256 threads, 64-row tile. Thread owns 4 cols x RPT rows.
// ---------------------------------------------------------------------------
template <int DC, bool RELU>
__global__ void k_gemm(const float* __restrict__ A, const float* __restrict__ W,
                       float* __restrict__ C, int nrows) {
    extern __shared__ float smem[];
    float* Ws = smem;              // 128 * DC
    float* As = smem + 128 * DC;   // 64 * 128

    constexpr int BR  = 64;
    constexpr int CG  = DC / 4;        // column-group threads
    constexpr int RG  = 256 / CG;      // row groups
    constexpr int RPT = BR / RG;       // rows per thread

    int row0 = blockIdx.x * BR;
    int rows = nrows - row0; if (rows > BR) rows = BR;

    for (int i = threadIdx.x; i < 128 * DC / 4; i += 256)
        ((float4*)Ws)[i] = ((const float4*)W)[i];

    for (int i = threadIdx.x; i < rows * 32; i += 256) {
        float4 v = ((const float4*)(A + (size_t)row0 * 128))[i];
        if (RELU) {
            v.x = fmaxf(v.x, 0.f); v.y = fmaxf(v.y, 0.f);
            v.z = fmaxf(v.z, 0.f); v.w = fmaxf(v.w, 0.f);
        }
        ((float4*)As)[i] = v;
    }
    __syncthreads();

    int tx = threadIdx.x % CG;
    int ty = threadIdx.x / CG;
    int r0 = ty * RPT;

    float acc[RPT][4];
#pragma unroll
    for (int r = 0; r < RPT; r++) { acc[r][0] = acc[r][1] = acc[r][2] = acc[r][3] = 0.f; }

    for (int k = 0; k < 128; k++) {
        float4 w = ((const float4*)Ws)[k * CG + tx];
#pragma unroll
        for (int r = 0; r < RPT; r++) {
            float a = As[(r0 + r) * 128 + k];
            acc[r][0] = fmaf(a, w.x, acc[r][0]);
            acc[r][1] = fmaf(a, w.y, acc[r][1]);
            acc[r][2] = fmaf(a, w.z, acc[r][2]);
            acc[r][3] = fmaf(a, w.w, acc[r][3]);
        }
    }

#pragma unroll
    for (int r = 0; r < RPT; r++) {
        int row = row0 + r0 + r;
        if (row < nrows) {
            float dv = g_dinv[row];
            float4 o = make_float4(acc[r][0] * dv, acc[r][1] * dv,
                                   acc[r][2] * dv, acc[r][3] * dv);
            ((float4*)(C + (size_t)row * DC))[tx] = o;
        }
    }
}

// ---------------------------------------------------------------------------
// Pull aggregation: out[d,:] = dinv[d] * ( sum_{s in N(d)} hs[s,:] + hs[d,:] ) + b
// one warp per node; lane handles float4 (128-d) or float2 (64-d).
// ---------------------------------------------------------------------------
__global__ void k_agg128(const float* __restrict__ hs, const float* __restrict__ b,
                         float* __restrict__ out, int n) {
    int node = (blockIdx.x * blockDim.x + threadIdx.x) >> 5;
    int lane = threadIdx.x & 31;
    if (node >= n) return;
    int beg = g_rowptr[node], end = g_rowptr[node + 1];

    float4 acc = *(const float4*)(hs + (size_t)node * 128 + lane * 4);  // self

    int e = beg;
    for (; e + 4 <= end; e += 4) {
        int s0 = g_eidx[e], s1 = g_eidx[e + 1], s2 = g_eidx[e + 2], s3 = g_eidx[e + 3];
        float4 v0 = *(const float4*)(hs + (size_t)s0 * 128 + lane * 4);
        float4 v1 = *(const float4*)(hs + (size_t)s1 * 128 + lane * 4);
        float4 v2 = *(const float4*)(hs + (size_t)s2 * 128 + lane * 4);
        float4 v3 = *(const float4*)(hs + (size_t)s3 * 128 + lane * 4);
        acc.x += (v0.x + v1.x) + (v2.x + v3.x);
        acc.y += (v0.y + v1.y) + (v2.y + v3.y);
        acc.z += (v0.z + v1.z) + (v2.z + v3.z);
        acc.w += (v0.w + v1.w) + (v2.w + v3.w);
    }
    for (; e < end; e++) {
        int s = g_eidx[e];
        float4 v = *(const float4*)(hs + (size_t)s * 128 + lane * 4);
        acc.x += v.x; acc.y += v.y; acc.z += v.z; acc.w += v.w;
    }

    float dv = g_dinv[node];
    float4 bb = ((const float4*)b)[lane];
    acc.x = fmaf(acc.x, dv, bb.x);
    acc.y = fmaf(acc.y, dv, bb.y);
    acc.z = fmaf(acc.z, dv, bb.z);
    acc.w = fmaf(acc.w, dv, bb.w);
    *(float4*)(out + (size_t)node * 128 + lane * 4) = acc;
}

__global__ void k_agg64(const float* __restrict__ hs, const float* __restrict__ b,
                        float* __restrict__ out, int n) {
    int node = (blockIdx.x * blockDim.x + threadIdx.x) >> 5;
    int lane = threadIdx.x & 31;
    if (node >= n) return;
    int beg = g_rowptr[node], end = g_rowptr[node + 1];

    float2 acc = *(const float2*)(hs + (size_t)node * 64 + lane * 2);  // self

    int e = beg;
    for (; e + 4 <= end; e += 4) {
        int s0 = g_eidx[e], s1 = g_eidx[e + 1], s2 = g_eidx[e + 2], s3 = g_eidx[e + 3];
        float2 v0 = *(const float2*)(hs + (size_t)s0 * 64 + lane * 2);
        float2 v1 = *(const float2*)(hs + (size_t)s1 * 64 + lane * 2);
        float2 v2 = *(const float2*)(hs + (size_t)s2 * 64 + lane * 2);
        float2 v3 = *(const float2*)(hs + (size_t)s3 * 64 + lane * 2);
        acc.x += (v0.x + v1.x) + (v2.x + v3.x);
        acc.y += (v0.y + v1.y) + (v2.y + v3.y);
    }
    for (; e < end; e++) {
        int s = g_eidx[e];
        float2 v = *(const float2*)(hs + (size_t)s * 64 + lane * 2);
        acc.x += v.x; acc.y += v.y;
    }

    float dv = g_dinv[node];
    float2 bb = ((const float2*)b)[lane];
    acc.x = fmaf(acc.x, dv, bb.x);
    acc.y = fmaf(acc.y, dv, bb.y);
    *(float2*)(out + (size_t)node * 64 + lane * 2) = acc;
}

// ---------------------------------------------------------------------------
extern "C" void kernel_launch(void* const* d_in, const int* in_sizes, int n_in,
                              void* d_out, int out_size) {
    const float* x  = (const float*)d_in[0];
    const int*   ei = (const int*)d_in[1];
    const float* W1 = (const float*)d_in[2];
    const float* b1 = (const float*)d_in[3];
    const float* W2 = (const float*)d_in[4];
    const float* b2 = (const float*)d_in[5];
    float* out = (float*)d_out;

    int n = in_sizes[0] / DIN_;
    int e = in_sizes[1] / 2;
    const int* src = ei;
    const int* dst = ei + e;

    cudaFuncSetAttribute(k_gemm<128, false>, cudaFuncAttributeMaxDynamicSharedMemorySize,
                         (128 * 128 + 64 * 128) * 4);
    cudaFuncSetAttribute(k_gemm<64, true>, cudaFuncAttributeMaxDynamicSharedMemorySize,
                         (128 * 64 + 64 * 128) * 4);

    const int T = 256;

    // CSR build (by dst)
    k_zero_cnt<<<(n + T - 1) / T, T>>>(n);
    k_count<<<(e + T - 1) / T, T>>>(dst, e);
    k_dinv<<<(n + T - 1) / T, T>>>(n);
    k_scan<<<1, 1024>>>(n);
    k_copycur<<<(n + T - 1) / T, T>>>(n);
    k_fill<<<(e + T - 1) / T, T>>>(src, dst, e);

    // layer 1
    k_gemm<128, false><<<(n + 63) / 64, 256, (128 * 128 + 64 * 128) * 4>>>(x, W1, g_hs1, n);
    k_agg128<<<(n * 32 + T - 1) / T, T>>>(g_hs1, b1, g_agg1, n);

    // layer 2
    k_gemm<64, true><<<(n + 63) / 64, 256, (128 * 64 + 64 * 128) * 4>>>(g_agg1, W2, g_hs2, n);
    k_agg64<<<(n * 32 + T - 1) / T, T>>>(g_hs2, b2, out, n);
}

// round 3
// speedup vs baseline: 1.7865x; 1.1051x over previous
#include <cuda_runtime.h>
#include <cuda_bf16.h>

#define NN    100000
#define EE    1600000
#define DIN_  128
#define DH_   128
#define DOUT_ 64

// ---------------------------------------------------------------------------
// Scratch (static device globals — allocation forbidden in kernel_launch)
// ---------------------------------------------------------------------------
__device__ int   g_cnt[NN];          // in-degree counts, then CSR cursor
__device__ int   g_rowptr[NN + 1];   // CSR row pointers (by dst)
__device__ int   g_bsum[256];        // per-block scan sums
__device__ int   g_eidx[EE];         // src node per CSR slot
__device__ float g_dinv[NN];
__device__ float g_hs1[(size_t)NN * DH_];    // (x @ W1) * dinv[row]
__device__ float g_agg1[(size_t)NN * DH_];   // layer-1 output (pre-relu)
__device__ float g_hs2[(size_t)NN * DOUT_];  // (relu(agg1) @ W2) * dinv[row]

// ---------------------------------------------------------------------------
// CSR construction
// ---------------------------------------------------------------------------
__global__ void k_zero_cnt(int n) {
    int i = blockIdx.x * blockDim.x + threadIdx.x;
    if (i < n) g_cnt[i] = 0;
}

__global__ void k_count(const int* __restrict__ dst, int e) {
    int i = blockIdx.x * blockDim.x + threadIdx.x;
    if (i < e) atomicAdd(&g_cnt[dst[i]], 1);
}

__global__ void k_dinv(int n) {
    int i = blockIdx.x * blockDim.x + threadIdx.x;
    if (i < n) g_dinv[i] = rsqrtf((float)g_cnt[i] + 1.0f);
}

// scan phase A: per-1024-block exclusive scan of g_cnt into g_rowptr (local),
// block total into g_bsum[b]
__global__ void k_scanA(int n) {
    __shared__ int sh[32];
    int b = blockIdx.x;
    int i = b * 1024 + (int)threadIdx.x;
    int lane = threadIdx.x & 31, wid = threadIdx.x >> 5;
    int v = (i < n) ? g_cnt[i] : 0;
    int x = v;
#pragma unroll
    for (int o = 1; o < 32; o <<= 1) {
        int t = __shfl_up_sync(0xffffffffu, x, o);
        if (lane >= o) x += t;
    }
    if (lane == 31) sh[wid] = x;
    __syncthreads();
    if (wid == 0) {
        int y = sh[lane];
#pragma unroll
        for (int o = 1; o < 32; o <<= 1) {
            int t = __shfl_up_sync(0xffffffffu, y, o);
            if (lane >= o) y += t;
        }
        sh[lane] = y;
    }
    __syncthreads();
    int excl = x - v + (wid > 0 ? sh[wid - 1] : 0);
    if (i < n) g_rowptr[i] = excl;
    if (threadIdx.x == 1023) g_bsum[b] = excl + v;
}

// scan phase B: exclusive scan of block sums (nb <= 128) in one 128-thread block
__global__ void k_scanB(int nb) {
    __shared__ int sh[4];
    int lane = threadIdx.x & 31, wid = threadIdx.x >> 5;
    int v = ((int)threadIdx.x < nb) ? g_bsum[threadIdx.x] : 0;
    int x = v;
#pragma unroll
    for (int o = 1; o < 32; o <<= 1) {
        int t = __shfl_up_sync(0xffffffffu, x, o);
        if (lane >= o) x += t;
    }
    if (lane == 31) sh[wid] = x;
    __syncthreads();
    int add = 0;
#pragma unroll
    for (int w = 0; w < 4; w++) add += (w < wid) ? sh[w] : 0;
    if ((int)threadIdx.x < nb) g_bsum[threadIdx.x] = x - v + add;
}

// scan phase C: add block offsets; finalize rowptr and init cursor
__global__ void k_scanC(int n, int e) {
    int i = blockIdx.x * blockDim.x + threadIdx.x;
    if (i < n) {
        int r = g_rowptr[i] + g_bsum[i >> 10];
        g_rowptr[i] = r;
        g_cnt[i] = r;
    }
    if (i == 0) g_rowptr[n] = e;
}

__global__ void k_fill(const int* __restrict__ src, const int* __restrict__ dst, int e) {
    int i = blockIdx.x * blockDim.x + threadIdx.x;
    if (i < e) {
        int pos = atomicAdd(&g_cnt[dst[i]], 1);
        g_eidx[pos] = src[i];
    }
}

// ---------------------------------------------------------------------------
// GEMM: C[row, :] = (relu?)(A[row, :128]) @ W[128, DC] * dinv[row]
// 256 threads, 64-row tile. A in smem (32KB), W streamed via __ldg (L1-hot).
// Thread owns 4 cols x RPT rows.
// ---------------------------------------------------------------------------
template <int DC, bool RELU>
__global__ void __launch_bounds__(256) k_gemm(const float* __restrict__ A,
                                              const float* __restrict__ W,
                                              float* __restrict__ C, int nrows) {
    __shared__ float As[64 * 128];

    constexpr int CG  = DC / 4;        // 32 (DC=128) or 16 (DC=64)
    constexpr int RG  = 256 / CG;      // 8 or 16
    constexpr int RPT = 64 / RG;       // 8 or 4

    int row0 = blockIdx.x * 64;
    int rows = nrows - row0; if (rows > 64) rows = 64;

    for (int i = threadIdx.x; i < rows * 32; i += 256) {
        float4 v = ((const float4*)(A + (size_t)row0 * 128))[i];
        if (RELU) {
            v.x = fmaxf(v.x, 0.f); v.y = fmaxf(v.y, 0.f);
            v.z = fmaxf(v.z, 0.f); v.w = fmaxf(v.w, 0.f);
        }
        ((float4*)As)[i] = v;
    }
    __syncthreads();

    int tx = threadIdx.x % CG;
    int ty = threadIdx.x / CG;
    int r0 = ty * RPT;

    float acc[RPT][4];
#pragma unroll
    for (int r = 0; r < RPT; r++) { acc[r][0] = acc[r][1] = acc[r][2] = acc[r][3] = 0.f; }

    const float4* W4 = (const float4*)W;
#pragma unroll 4
    for (int k = 0; k < 128; k++) {
        float4 w = __ldg(&W4[k * CG + tx]);
#pragma unroll
        for (int r = 0; r < RPT; r++) {
            float a = As[(r0 + r) * 128 + k];
            acc[r][0] = fmaf(a, w.x, acc[r][0]);
            acc[r][1] = fmaf(a, w.y, acc[r][1]);
            acc[r][2] = fmaf(a, w.z, acc[r][2]);
            acc[r][3] = fmaf(a, w.w, acc[r][3]);
        }
    }

#pragma unroll
    for (int r = 0; r < RPT; r++) {
        int row = row0 + r0 + r;
        if (row < nrows) {
            float dv = g_dinv[row];
            float4 o = make_float4(acc[r][0] * dv, acc[r][1] * dv,
                                   acc[r][2] * dv, acc[r][3] * dv);
            ((float4*)(C + (size_t)row * DC))[tx] = o;
        }
    }
}

// ---------------------------------------------------------------------------
// Pull aggregation: out[d,:] = dinv[d] * ( sum_{s in N(d)} hs[s,:] + hs[d,:] ) + b
// one warp per node; 8-deep unrolled gather for MLP.
// ---------------------------------------------------------------------------
__global__ void k_agg128(const float* __restrict__ hs, const float* __restrict__ b,
                         float* __restrict__ out, int n) {
    int node = (blockIdx.x * blockDim.x + threadIdx.x) >> 5;
    int lane = threadIdx.x & 31;
    if (node >= n) return;
    int beg = g_rowptr[node], end = g_rowptr[node + 1];

    float4 acc = *(const float4*)(hs + (size_t)node * 128 + lane * 4);  // self

    int e = beg;
    for (; e + 8 <= end; e += 8) {
        int s[8];
#pragma unroll
        for (int j = 0; j < 8; j++) s[j] = g_eidx[e + j];
        float4 v[8];
#pragma unroll
        for (int j = 0; j < 8; j++)
            v[j] = *(const float4*)(hs + (size_t)s[j] * 128 + lane * 4);
#pragma unroll
        for (int j = 0; j < 8; j++) {
            acc.x += v[j].x; acc.y += v[j].y; acc.z += v[j].z; acc.w += v[j].w;
        }
    }
    for (; e < end; e++) {
        int s = g_eidx[e];
        float4 v = *(const float4*)(hs + (size_t)s * 128 + lane * 4);
        acc.x += v.x; acc.y += v.y; acc.z += v.z; acc.w += v.w;
    }

    float dv = g_dinv[node];
    float4 bb = ((const float4*)b)[lane];
    acc.x = fmaf(acc.x, dv, bb.x);
    acc.y = fmaf(acc.y, dv, bb.y);
    acc.z = fmaf(acc.z, dv, bb.z);
    acc.w = fmaf(acc.w, dv, bb.w);
    *(float4*)(out + (size_t)node * 128 + lane * 4) = acc;
}

__global__ void k_agg64(const float* __restrict__ hs, const float* __restrict__ b,
                        float* __restrict__ out, int n) {
    int node = (blockIdx.x * blockDim.x + threadIdx.x) >> 5;
    int lane = threadIdx.x & 31;
    if (node >= n) return;
    int beg = g_rowptr[node], end = g_rowptr[node + 1];

    float2 acc = *(const float2*)(hs + (size_t)node * 64 + lane * 2);  // self

    int e = beg;
    for (; e + 8 <= end; e += 8) {
        int s[8];
#pragma unroll
        for (int j = 0; j < 8; j++) s[j] = g_eidx[e + j];
        float2 v[8];
#pragma unroll
        for (int j = 0; j < 8; j++)
            v[j] = *(const float2*)(hs + (size_t)s[j] * 64 + lane * 2);
#pragma unroll
        for (int j = 0; j < 8; j++) { acc.x += v[j].x; acc.y += v[j].y; }
    }
    for (; e < end; e++) {
        int s = g_eidx[e];
        float2 v = *(const float2*)(hs + (size_t)s * 64 + lane * 2);
        acc.x += v.x; acc.y += v.y;
    }

    float dv = g_dinv[node];
    float2 bb = ((const float2*)b)[lane];
    acc.x = fmaf(acc.x, dv, bb.x);
    acc.y = fmaf(acc.y, dv, bb.y);
    *(float2*)(out + (size_t)node * 64 + lane * 2) = acc;
}

// ---------------------------------------------------------------------------
extern "C" void kernel_launch(void* const* d_in, const int* in_sizes, int n_in,
                              void* d_out, int out_size) {
    const float* x  = (const float*)d_in[0];
    const int*   ei = (const int*)d_in[1];
    const float* W1 = (const float*)d_in[2];
    const float* b1 = (const float*)d_in[3];
    const float* W2 = (const float*)d_in[4];
    const float* b2 = (const float*)d_in[5];
    float* out = (float*)d_out;

    int n = in_sizes[0] / DIN_;
    int e = in_sizes[1] / 2;
    const int* src = ei;
    const int* dst = ei + e;

    const int T = 256;
    int nb = (n + 1023) / 1024;

    // launch 0-2: degree + dinv
    k_zero_cnt<<<(n + T - 1) / T, T>>>(n);
    k_count<<<(e + T - 1) / T, T>>>(dst, e);
    k_dinv<<<(n + T - 1) / T, T>>>(n);

    // launch 3: gemm1  (profiled slot)
    k_gemm<128, false><<<(n + 63) / 64, 256>>>(x, W1, g_hs1, n);

    // launch 4-7: CSR build
    k_scanA<<<nb, 1024>>>(n);
    k_scanB<<<1, 128>>>(nb);
    k_scanC<<<(n + T - 1) / T, T>>>(n, e);
    k_fill<<<(e + T - 1) / T, T>>>(src, dst, e);

    // launch 8: layer-1 aggregation
    k_agg128<<<(n * 32 + T - 1) / T, T>>>(g_hs1, b1, g_agg1, n);

    // launch 9-10: layer 2
    k_gemm<64, true><<<(n + 63) / 64, 256>>>(g_agg1, W2, g_hs2, n);
    k_agg64<<<(n * 32 + T - 1) / T, T>>>(g_hs2, b2, out, n);
}